// round 12
// baseline (speedup 1.0000x reference)
#include <cuda_runtime.h>
#include <cuda_fp16.h>
#include <cstdint>

// ---------------------------------------------------------------------------
// SelfAttention  x[4,2048,1024] -> out[4,2048,1024]
// Round 12: r11 + 4-stage cp.async pipeline (deeper load slack) +
//           programmatic dependent launch (PDL) chaining the 5 kernels.
// ---------------------------------------------------------------------------

#define BATCH 4
#define SEQ   2048
#define DM    1024

// ---- scratch (__device__ globals) ----
__device__ __half g_xh   [(long long)BATCH * SEQ * DM];
__device__ __half g_wqkvt[3 * DM * DM];
__device__ __half g_wot  [DM * DM];
__device__ float  g_bqkv [3 * DM];
__device__ __half g_q  [(long long)BATCH * SEQ * DM];
__device__ __half g_k  [(long long)BATCH * SEQ * DM];
__device__ __half g_v  [(long long)BATCH * SEQ * DM];
__device__ __half g_p  [(long long)BATCH * SEQ * SEQ];   // exp(scores), half
__device__ float  g_rs [BATCH * SEQ];                    // row sums
__device__ __half g_o  [(long long)BATCH * SEQ * DM];

// ---- PTX helpers ----
__device__ __forceinline__ void cp_async16(void* smem, const void* gmem) {
    uint32_t s = (uint32_t)__cvta_generic_to_shared(smem);
    asm volatile("cp.async.ca.shared.global [%0], [%1], 16;\n" :: "r"(s), "l"(gmem));
}
#define CP_COMMIT() asm volatile("cp.async.commit_group;\n" ::: "memory")
#define CP_WAIT2()  asm volatile("cp.async.wait_group 2;\n" ::: "memory")

#define PDL_WAIT()    asm volatile("griddepcontrol.wait;" ::: "memory")
#define PDL_TRIGGER() asm volatile("griddepcontrol.launch_dependents;" ::: "memory")

__device__ __forceinline__ void mma_f16(float* c, const uint32_t* a, const uint32_t* b) {
    asm volatile(
        "mma.sync.aligned.m16n8k16.row.col.f32.f16.f16.f32 "
        "{%0,%1,%2,%3}, {%4,%5,%6,%7}, {%8,%9}, {%0,%1,%2,%3};\n"
        : "+f"(c[0]), "+f"(c[1]), "+f"(c[2]), "+f"(c[3])
        : "r"(a[0]), "r"(a[1]), "r"(a[2]), "r"(a[3]), "r"(b[0]), "r"(b[1]));
}

__device__ __forceinline__ void ldmatrix_x4(uint32_t* r, uint32_t saddr) {
    asm volatile("ldmatrix.sync.aligned.m8n8.x4.shared.b16 {%0,%1,%2,%3}, [%4];"
        : "=r"(r[0]), "=r"(r[1]), "=r"(r[2]), "=r"(r[3]) : "r"(saddr));
}
__device__ __forceinline__ void ldmatrix_x4_trans(uint32_t* r, uint32_t saddr) {
    asm volatile("ldmatrix.sync.aligned.m8n8.x4.trans.shared.b16 {%0,%1,%2,%3}, [%4];"
        : "=r"(r[0]), "=r"(r[1]), "=r"(r[2]), "=r"(r[3]) : "r"(saddr));
}

// ---------------------------------------------------------------------------
// FP16 GEMM: C = scale*(A[M,K] @ op(B)) [+ bias]
// CTA 128x256x64, 256 thr, 8 warps (2x4), warp tile 64x64, 4-stage cp.async.
// MODE: 0=QKV (B=[N,K] NT; half out, bias, route by n-block)
//       1=scores->exp (B=[N,K] NT; half out = exp(acc*scale); atomic row sums)
//       2=PV (B=v[K,N] via ldmatrix.trans; half out, /rowsum via 'bias' slot)
//       3=outproj (B=[N,K] NT; f32 out, bias)
// ---------------------------------------------------------------------------
#define BM 128
#define BN 256
#define BKH 64                   // K halves per stage
#define PITCH 72                 // NT pitch: 144B rows (conflict-free)
#define VPITCH 264               // MODE2 B pitch: 528B rows (conflict-free)
#define ASTH (BM * PITCH)        // 9216 halves
#define BSTH (BN * PITCH)        // 18432 halves (MODE2 uses BKH*VPITCH=16896)
#define STG_H (ASTH + BSTH)      // 27648 halves per stage
#define STAGES 4
#define GEMM_SMEM (STAGES * STG_H * 2)   // 221184 bytes
#define NTHR 256

template<int MODE>
__global__ __launch_bounds__(NTHR, 1)
void gemm_h(const __half* __restrict__ A, const __half* __restrict__ B,
            const float* __restrict__ bias,
            void* __restrict__ C0, void* __restrict__ C1, void* __restrict__ C2,
            int N, int K, float scale,
            long long strA, long long strB, long long strC)
{
    extern __shared__ __half smem[];
    const uint32_t sbase = (uint32_t)__cvta_generic_to_shared(smem);

    const int bz = blockIdx.z;
    A += (long long)bz * strA;
    B += (long long)bz * strB;

    const int m0 = blockIdx.y * BM;
    const int n0 = blockIdx.x * BN;
    const int t    = threadIdx.x;
    const int lane = t & 31;
    const int wid  = t >> 5;
    const int warp_m = wid & 1;     // 0..1 (64 rows)
    const int warp_n = wid >> 1;    // 0..3 (64 cols)
    const int gid = lane >> 2;
    const int tig = lane & 3;

    // ldmatrix per-lane source coords
    const int rowA = warp_m * 64 + (lane & 15);      // + mf*16
    const int colA = (lane >> 4) * 8;                // + kk
    const int gB   = lane >> 3;
    const int rowB = warp_n * 64 + (gB >> 1) * 8 + (lane & 7);  // NT: + p*16
    const int colB = (gB & 1) * 8;
    // MODE2 trans coords
    const int kln = lane & 15;
    const int nln = (lane >> 4) * 8;

    float acc[4][8][4];
    #pragma unroll
    for (int mf = 0; mf < 4; mf++)
        #pragma unroll
        for (int nf = 0; nf < 8; nf++)
            #pragma unroll
            for (int r = 0; r < 4; r++) acc[mf][nf][r] = 0.f;

    const int KT = K / BKH;

    auto load_tiles = [&](int stage, int kt) {
        const int k0 = kt * BKH;
        __half* dA = smem + stage * STG_H;
        __half* dB = dA + ASTH;
        #pragma unroll
        for (int i = 0; i < 4; i++) {           // A: 1024 16B chunks
            int ch = t + i * NTHR;
            int row = ch >> 3, c8 = (ch & 7) * 8;
            cp_async16(dA + row * PITCH + c8, A + (long long)(m0 + row) * K + k0 + c8);
        }
        if (MODE == 2) {
            #pragma unroll
            for (int i = 0; i < 8; i++) {       // v tile: 64 rows x 512B
                int ch = t + i * NTHR;
                int row = ch >> 5, c8 = (ch & 31) * 8;
                cp_async16(dB + row * VPITCH + c8,
                           B + (long long)(k0 + row) * DM + n0 + c8);
            }
        } else {
            #pragma unroll
            for (int i = 0; i < 8; i++) {       // B NT: 2048 16B chunks
                int ch = t + i * NTHR;
                int row = ch >> 3, c8 = (ch & 7) * 8;
                cp_async16(dB + row * PITCH + c8, B + (long long)(n0 + row) * K + k0 + c8);
            }
        }
    };

    // PDL: wait for predecessor kernel's writes before first global read
    PDL_WAIT();

    // prologue: stages 0,1,2
    load_tiles(0, 0); CP_COMMIT();
    if (1 < KT) load_tiles(1, 1);
    CP_COMMIT();
    if (2 < KT) load_tiles(2, 2);
    CP_COMMIT();

    int stage = 0;
    for (int kt = 0; kt < KT; kt++) {
        CP_WAIT2();
        __syncthreads();          // stage kt ready; all warps done with kt-1

        if (kt + 3 < KT) {
            int ns = stage + 3; if (ns >= STAGES) ns -= STAGES;
            load_tiles(ns, kt + 3);
        }
        CP_COMMIT();

        const uint32_t aS = sbase + (stage * STG_H) * 2;
        const uint32_t bS = aS + ASTH * 2;

        #pragma unroll
        for (int kk = 0; kk < BKH; kk += 16) {
            uint32_t af[4][4];
            #pragma unroll
            for (int mf = 0; mf < 4; mf++)
                ldmatrix_x4(af[mf], aS + (uint32_t)(((rowA + mf * 16) * PITCH) + kk + colA) * 2);
            uint32_t bf[8][2];
            #pragma unroll
            for (int p = 0; p < 4; p++) {
                uint32_t r[4];
                if (MODE == 2) {
                    ldmatrix_x4_trans(r, bS + (uint32_t)((kk + kln) * VPITCH +
                                           warp_n * 64 + p * 16 + nln) * 2);
                } else {
                    ldmatrix_x4(r, bS + (uint32_t)(((rowB + p * 16) * PITCH) + kk + colB) * 2);
                }
                bf[2 * p][0] = r[0]; bf[2 * p][1] = r[1];
                bf[2 * p + 1][0] = r[2]; bf[2 * p + 1][1] = r[3];
            }
            #pragma unroll
            for (int mf = 0; mf < 4; mf++)
                #pragma unroll
                for (int nf = 0; nf < 8; nf++)
                    mma_f16(acc[mf][nf], af[mf], bf[nf]);
        }
        if (++stage >= STAGES) stage = 0;
    }

    // PDL: our remaining work is epilogue only; let dependents spin up
    PDL_TRIGGER();

    // ---- epilogue ----
    __half* Ch; float* Cf; int Nout = N;
    int ncol0 = n0;
    float* rsum = nullptr;
    if (MODE == 0) {            // QKV: route by 1024-block
        const int blk = n0 >> 10;
        Ch = (__half*)(blk == 0 ? C0 : (blk == 1 ? C1 : C2));
        Ch += (long long)bz * strC;
        ncol0 = n0 & 1023; Nout = DM;
    } else if (MODE == 1) {
        Ch = (__half*)C0 + (long long)bz * strC;
        rsum = (float*)C1 + (long long)bz * SEQ;
    } else if (MODE == 2) {
        Ch = (__half*)C0 + (long long)bz * strC;
        rsum = (float*)bias + (long long)bz * SEQ;   // rowsum passed via bias slot
    } else {
        Cf = (float*)C0 + (long long)bz * strC;
    }

    #pragma unroll
    for (int mf = 0; mf < 4; mf++) {
        const int r0 = m0 + warp_m * 64 + mf * 16 + gid;
        float inv0 = 1.f, inv1 = 1.f;
        if (MODE == 2) {
            inv0 = 1.f / rsum[r0];
            inv1 = 1.f / rsum[r0 + 8];
        }
        float psum0 = 0.f, psum8 = 0.f;   // MODE==1 row partial sums
        #pragma unroll
        for (int nf = 0; nf < 8; nf++) {
            const int nrel = warp_n * 64 + nf * 8 + 2 * tig;
            const int n = ncol0 + nrel;
            float bx = 0.f, by = 0.f;
            if (MODE == 0 || MODE == 3) {
                float2 bv = *(const float2*)&bias[n0 + nrel];
                bx = bv.x; by = bv.y;
            }
            float c0 = acc[mf][nf][0] * scale + bx;
            float c1 = acc[mf][nf][1] * scale + by;
            float c2 = acc[mf][nf][2] * scale + bx;
            float c3 = acc[mf][nf][3] * scale + by;
            if (MODE == 1) {
                __half2 e01 = __floats2half2_rn(__expf(c0), __expf(c1));
                __half2 e23 = __floats2half2_rn(__expf(c2), __expf(c3));
                float2 f01 = __half22float2(e01);
                float2 f23 = __half22float2(e23);
                psum0 += f01.x + f01.y;
                psum8 += f23.x + f23.y;
                *(__half2*)&Ch[(long long)r0 * Nout + n]       = e01;
                *(__half2*)&Ch[(long long)(r0 + 8) * Nout + n] = e23;
            } else if (MODE == 2) {
                *(__half2*)&Ch[(long long)r0 * Nout + n]       = __floats2half2_rn(c0 * inv0, c1 * inv0);
                *(__half2*)&Ch[(long long)(r0 + 8) * Nout + n] = __floats2half2_rn(c2 * inv1, c3 * inv1);
            } else if (MODE == 0) {
                *(__half2*)&Ch[(long long)r0 * Nout + n]       = __floats2half2_rn(c0, c1);
                *(__half2*)&Ch[(long long)(r0 + 8) * Nout + n] = __floats2half2_rn(c2, c3);
            } else {
                *(float2*)&Cf[(long long)r0 * Nout + n]       = make_float2(c0, c1);
                *(float2*)&Cf[(long long)(r0 + 8) * Nout + n] = make_float2(c2, c3);
            }
        }
        if (MODE == 1) {
            psum0 += __shfl_xor_sync(0xffffffffu, psum0, 1);
            psum0 += __shfl_xor_sync(0xffffffffu, psum0, 2);
            psum8 += __shfl_xor_sync(0xffffffffu, psum8, 1);
            psum8 += __shfl_xor_sync(0xffffffffu, psum8, 2);
            if (tig == 0) {
                atomicAdd(&rsum[r0], psum0);
                atomicAdd(&rsum[r0 + 8], psum8);
            }
        }
    }
}

// ---------------------------------------------------------------------------
// Fused prepass (one launch): f2h + 4x weight transpose + bias concat + rs zero
// ---------------------------------------------------------------------------
struct PrepassArgs {
    const float* x;  __half* xh;
    const float* w[4]; __half* wt[4];
    const float* bq; const float* bk; const float* bv;
    float* bqkv; float* rs;
};

__global__ __launch_bounds__(256)
void prepass_all(PrepassArgs pa)
{
    const int b = blockIdx.x;
    const int t = threadIdx.x;
    if (b < 4096) {
        long long i = ((long long)b * 256 + t) * 8;
        float4 a = *(const float4*)(pa.x + i);
        float4 c = *(const float4*)(pa.x + i + 4);
        __half2 h[4];
        h[0] = __floats2half2_rn(a.x, a.y);
        h[1] = __floats2half2_rn(a.z, a.w);
        h[2] = __floats2half2_rn(c.x, c.y);
        h[3] = __floats2half2_rn(c.z, c.w);
        *(uint4*)(pa.xh + i) = *(uint4*)h;
    } else if (b < 8192) {
        __shared__ float tl[32][33];
        const int bb = b - 4096;
        const int wsel = bb >> 10;
        const int tile = bb & 1023;
        const int bx = tile & 31, by = tile >> 5;
        const float* in = pa.w[wsel];
        __half* outw = pa.wt[wsel];
        const int tx = t & 31, ty = t >> 5;
        const int c = bx * 32 + tx;
        const int r0 = by * 32;
        #pragma unroll
        for (int i = 0; i < 32; i += 8)
            tl[ty + i][tx] = in[(long long)(r0 + ty + i) * DM + c];
        __syncthreads();
        const int r2 = r0 + tx;
        const int c2 = bx * 32;
        #pragma unroll
        for (int i = 0; i < 32; i += 8)
            outw[(long long)(c2 + ty + i) * DM + r2] = __float2half_rn(tl[tx][ty + i]);
    } else {
        const int i = (b - 8192) * 256 + t;
        if (i < 3 * DM) {
            const float* src = (i < DM) ? pa.bq : (i < 2 * DM ? pa.bk : pa.bv);
            pa.bqkv[i] = src[i & (DM - 1)];
        }
        const int j = i - 3 * DM;
        if (j >= 0 && j < BATCH * SEQ) pa.rs[j] = 0.f;
    }
    PDL_TRIGGER();
}

// ---------------------------------------------------------------------------
extern "C" void kernel_launch(void* const* d_in, const int* in_sizes, int n_in,
                              void* d_out, int out_size)
{
    const float* x  = (const float*)d_in[0];
    const float* wq = (const float*)d_in[1];
    const float* bq = (const float*)d_in[2];
    const float* wk = (const float*)d_in[3];
    const float* bk = (const float*)d_in[4];
    const float* wv = (const float*)d_in[5];
    const float* bv = (const float*)d_in[6];
    const float* wo = (const float*)d_in[7];
    const float* bo = (const float*)d_in[8];
    float* out = (float*)d_out;

    __half *xh, *wqkvt, *wot, *q, *k, *v, *pm, *o;
    float *bqkv, *rs;
    cudaGetSymbolAddress((void**)&xh,    g_xh);
    cudaGetSymbolAddress((void**)&wqkvt, g_wqkvt);
    cudaGetSymbolAddress((void**)&wot,   g_wot);
    cudaGetSymbolAddress((void**)&bqkv,  g_bqkv);
    cudaGetSymbolAddress((void**)&q,   g_q);
    cudaGetSymbolAddress((void**)&k,   g_k);
    cudaGetSymbolAddress((void**)&v,   g_v);
    cudaGetSymbolAddress((void**)&pm,  g_p);
    cudaGetSymbolAddress((void**)&rs,  g_rs);
    cudaGetSymbolAddress((void**)&o,   g_o);

    cudaFuncSetAttribute(gemm_h<0>, cudaFuncAttributeMaxDynamicSharedMemorySize, GEMM_SMEM);
    cudaFuncSetAttribute(gemm_h<1>, cudaFuncAttributeMaxDynamicSharedMemorySize, GEMM_SMEM);
    cudaFuncSetAttribute(gemm_h<2>, cudaFuncAttributeMaxDynamicSharedMemorySize, GEMM_SMEM);
    cudaFuncSetAttribute(gemm_h<3>, cudaFuncAttributeMaxDynamicSharedMemorySize, GEMM_SMEM);

    const int MTOT = BATCH * SEQ;      // 8192
    const float iscale = 0.03125f;     // 1/sqrt(1024)

    // --- fused prepass (plain launch; triggers PDL for QKV) ---
    PrepassArgs pa;
    pa.x = x; pa.xh = xh;
    pa.w[0] = wq; pa.w[1] = wk; pa.w[2] = wv; pa.w[3] = wo;
    pa.wt[0] = wqkvt; pa.wt[1] = wqkvt + DM * DM; pa.wt[2] = wqkvt + 2 * DM * DM;
    pa.wt[3] = wot;
    pa.bq = bq; pa.bk = bk; pa.bv = bv; pa.bqkv = bqkv; pa.rs = rs;
    prepass_all<<<8192 + 44, 256>>>(pa);

    // --- GEMM chain with PDL ---
    cudaLaunchAttribute attrs[1];
    attrs[0].id = cudaLaunchAttributeProgrammaticStreamSerialization;
    attrs[0].val.programmaticStreamSerializationAllowed = 1;

    cudaLaunchConfig_t cfg = {};
    cfg.blockDim = {NTHR, 1, 1};
    cfg.dynamicSmemBytes = GEMM_SMEM;
    cfg.attrs = attrs;
    cfg.numAttrs = 1;

    // fused QKV projection: N=3072, routed epilogue
    cfg.gridDim = {3 * DM / BN, MTOT / BM, 1};   // (12, 64)
    cudaLaunchKernelEx(&cfg, gemm_h<0>,
        (const __half*)xh, (const __half*)wqkvt, (const float*)bqkv,
        (void*)q, (void*)k, (void*)v,
        (int)(3 * DM), (int)DM, 1.0f, 0LL, 0LL, 0LL);

    // exp(scores) = exp(q @ k^T * (1/32)) -> half, + row sums (atomic)
    cfg.gridDim = {SEQ / BN, SEQ / BM, BATCH};   // (8, 16, 4)
    cudaLaunchKernelEx(&cfg, gemm_h<1>,
        (const __half*)q, (const __half*)k, (const float*)nullptr,
        (void*)pm, (void*)rs, (void*)nullptr,
        (int)SEQ, (int)DM, iscale,
        (long long)SEQ * DM, (long long)SEQ * DM, (long long)SEQ * SEQ);

    // o = (expS @ v) / rowsum  (B = v via ldmatrix.trans) -> half
    cfg.gridDim = {DM / BN, SEQ / BM, BATCH};    // (4, 16, 4)
    cudaLaunchKernelEx(&cfg, gemm_h<2>,
        (const __half*)pm, (const __half*)v, (const float*)rs,
        (void*)o, (void*)nullptr, (void*)nullptr,
        (int)DM, (int)SEQ, 1.0f,
        (long long)SEQ * SEQ, (long long)SEQ * DM, (long long)SEQ * DM);

    // out = o @ wo + bo -> fp32
    cfg.gridDim = {DM / BN, MTOT / BM, 1};       // (4, 64)
    cudaLaunchKernelEx(&cfg, gemm_h<3>,
        (const __half*)o, (const __half*)wot, (const float*)bo,
        (void*)out, (void*)nullptr, (void*)nullptr,
        (int)DM, (int)DM, 1.0f, 0LL, 0LL, 0LL);
}

// round 13
// speedup vs baseline: 1.2437x; 1.2437x over previous
#include <cuda_runtime.h>
#include <cuda_fp16.h>
#include <cstdint>

// ---------------------------------------------------------------------------
// SelfAttention  x[4,2048,1024] -> out[4,2048,1024]
// Round 13: revert r12 (back to 3-stage, plain launches) = best-known config;
//           micro-reorder k-tile head: kk=0 ldmatrix before cp.async prefetch
//           so HMMA issue isn't queued behind the 12-deep cp.async burst.
// ---------------------------------------------------------------------------

#define BATCH 4
#define SEQ   2048
#define DM    1024

// ---- scratch (__device__ globals) ----
__device__ __half g_xh   [(long long)BATCH * SEQ * DM];
__device__ __half g_wqkvt[3 * DM * DM];
__device__ __half g_wot  [DM * DM];
__device__ float  g_bqkv [3 * DM];
__device__ __half g_q  [(long long)BATCH * SEQ * DM];
__device__ __half g_k  [(long long)BATCH * SEQ * DM];
__device__ __half g_v  [(long long)BATCH * SEQ * DM];
__device__ __half g_p  [(long long)BATCH * SEQ * SEQ];   // exp(scores), half
__device__ float  g_rs [BATCH * SEQ];                    // row sums
__device__ __half g_o  [(long long)BATCH * SEQ * DM];

// ---- PTX helpers ----
__device__ __forceinline__ void cp_async16(void* smem, const void* gmem) {
    uint32_t s = (uint32_t)__cvta_generic_to_shared(smem);
    asm volatile("cp.async.ca.shared.global [%0], [%1], 16;\n" :: "r"(s), "l"(gmem));
}
#define CP_COMMIT() asm volatile("cp.async.commit_group;\n" ::: "memory")
#define CP_WAIT1()  asm volatile("cp.async.wait_group 1;\n" ::: "memory")

__device__ __forceinline__ void mma_f16(float* c, const uint32_t* a, const uint32_t* b) {
    asm volatile(
        "mma.sync.aligned.m16n8k16.row.col.f32.f16.f16.f32 "
        "{%0,%1,%2,%3}, {%4,%5,%6,%7}, {%8,%9}, {%0,%1,%2,%3};\n"
        : "+f"(c[0]), "+f"(c[1]), "+f"(c[2]), "+f"(c[3])
        : "r"(a[0]), "r"(a[1]), "r"(a[2]), "r"(a[3]), "r"(b[0]), "r"(b[1]));
}

__device__ __forceinline__ void ldmatrix_x4(uint32_t* r, uint32_t saddr) {
    asm volatile("ldmatrix.sync.aligned.m8n8.x4.shared.b16 {%0,%1,%2,%3}, [%4];"
        : "=r"(r[0]), "=r"(r[1]), "=r"(r[2]), "=r"(r[3]) : "r"(saddr));
}
__device__ __forceinline__ void ldmatrix_x4_trans(uint32_t* r, uint32_t saddr) {
    asm volatile("ldmatrix.sync.aligned.m8n8.x4.trans.shared.b16 {%0,%1,%2,%3}, [%4];"
        : "=r"(r[0]), "=r"(r[1]), "=r"(r[2]), "=r"(r[3]) : "r"(saddr));
}

// ---------------------------------------------------------------------------
// FP16 GEMM: C = scale*(A[M,K] @ op(B)) [+ bias]
// CTA 128x256x64, 256 thr, 8 warps (2x4), warp tile 64x64, 3-stage cp.async.
// MODE: 0=QKV (B=[N,K] NT; half out, bias, route by n-block)
//       1=scores->exp (B=[N,K] NT; half out = exp(acc*scale); atomic row sums)
//       2=PV (B=v[K,N] via ldmatrix.trans; half out, /rowsum via 'bias' slot)
//       3=outproj (B=[N,K] NT; f32 out, bias)
// ---------------------------------------------------------------------------
#define BM 128
#define BN 256
#define BKH 64                   // K halves per stage
#define PITCH 72                 // NT pitch: 144B rows (conflict-free)
#define VPITCH 264               // MODE2 B pitch: 528B rows (conflict-free)
#define ASTH (BM * PITCH)        // 9216 halves
#define BSTH (BN * PITCH)        // 18432 halves (MODE2 uses BKH*VPITCH=16896)
#define STG_H (ASTH + BSTH)      // 27648 halves per stage
#define STAGES 3
#define GEMM_SMEM (STAGES * STG_H * 2)   // 165888 bytes
#define NTHR 256

template<int MODE>
__global__ __launch_bounds__(NTHR, 1)
void gemm_h(const __half* __restrict__ A, const __half* __restrict__ B,
            const float* __restrict__ bias,
            void* __restrict__ C0, void* __restrict__ C1, void* __restrict__ C2,
            int N, int K, float scale,
            long long strA, long long strB, long long strC)
{
    extern __shared__ __half smem[];
    const uint32_t sbase = (uint32_t)__cvta_generic_to_shared(smem);

    const int bz = blockIdx.z;
    A += (long long)bz * strA;
    B += (long long)bz * strB;

    const int m0 = blockIdx.y * BM;
    const int n0 = blockIdx.x * BN;
    const int t    = threadIdx.x;
    const int lane = t & 31;
    const int wid  = t >> 5;
    const int warp_m = wid & 1;     // 0..1 (64 rows)
    const int warp_n = wid >> 1;    // 0..3 (64 cols)
    const int gid = lane >> 2;
    const int tig = lane & 3;

    // ldmatrix per-lane source coords
    const int rowA = warp_m * 64 + (lane & 15);      // + mf*16
    const int colA = (lane >> 4) * 8;                // + kk
    const int gB   = lane >> 3;
    const int rowB = warp_n * 64 + (gB >> 1) * 8 + (lane & 7);  // NT: + p*16
    const int colB = (gB & 1) * 8;
    // MODE2 trans coords
    const int kln = lane & 15;
    const int nln = (lane >> 4) * 8;

    float acc[4][8][4];
    #pragma unroll
    for (int mf = 0; mf < 4; mf++)
        #pragma unroll
        for (int nf = 0; nf < 8; nf++)
            #pragma unroll
            for (int r = 0; r < 4; r++) acc[mf][nf][r] = 0.f;

    const int KT = K / BKH;

    auto load_tiles = [&](int stage, int kt) {
        const int k0 = kt * BKH;
        __half* dA = smem + stage * STG_H;
        __half* dB = dA + ASTH;
        #pragma unroll
        for (int i = 0; i < 4; i++) {           // A: 1024 16B chunks
            int ch = t + i * NTHR;
            int row = ch >> 3, c8 = (ch & 7) * 8;
            cp_async16(dA + row * PITCH + c8, A + (long long)(m0 + row) * K + k0 + c8);
        }
        if (MODE == 2) {
            #pragma unroll
            for (int i = 0; i < 8; i++) {       // v tile: 64 rows x 512B
                int ch = t + i * NTHR;
                int row = ch >> 5, c8 = (ch & 31) * 8;
                cp_async16(dB + row * VPITCH + c8,
                           B + (long long)(k0 + row) * DM + n0 + c8);
            }
        } else {
            #pragma unroll
            for (int i = 0; i < 8; i++) {       // B NT: 2048 16B chunks
                int ch = t + i * NTHR;
                int row = ch >> 3, c8 = (ch & 7) * 8;
                cp_async16(dB + row * PITCH + c8, B + (long long)(n0 + row) * K + k0 + c8);
            }
        }
    };

    // fragment loader for one kk16 slice
    auto load_frags = [&](uint32_t aS, uint32_t bS, int kk,
                          uint32_t (&af)[4][4], uint32_t (&bf)[8][2]) {
        #pragma unroll
        for (int mf = 0; mf < 4; mf++)
            ldmatrix_x4(af[mf], aS + (uint32_t)(((rowA + mf * 16) * PITCH) + kk + colA) * 2);
        #pragma unroll
        for (int p = 0; p < 4; p++) {
            uint32_t r[4];
            if (MODE == 2) {
                ldmatrix_x4_trans(r, bS + (uint32_t)((kk + kln) * VPITCH +
                                       warp_n * 64 + p * 16 + nln) * 2);
            } else {
                ldmatrix_x4(r, bS + (uint32_t)(((rowB + p * 16) * PITCH) + kk + colB) * 2);
            }
            bf[2 * p][0] = r[0]; bf[2 * p][1] = r[1];
            bf[2 * p + 1][0] = r[2]; bf[2 * p + 1][1] = r[3];
        }
    };

    // prologue: stages 0,1
    load_tiles(0, 0); CP_COMMIT();
    if (1 < KT) load_tiles(1, 1);
    CP_COMMIT();

    int stage = 0;
    for (int kt = 0; kt < KT; kt++) {
        CP_WAIT1();
        __syncthreads();          // stage kt ready; all warps done with kt-1

        const uint32_t aS = sbase + (stage * STG_H) * 2;
        const uint32_t bS = aS + ASTH * 2;

        // kk=0 fragments FIRST, so HMMA can start before the cp.async burst
        uint32_t af[4][4];
        uint32_t bf[8][2];
        load_frags(aS, bS, 0, af, bf);

        // now issue next-stage prefetch
        if (kt + 2 < KT) {
            int ns = stage + 2; if (ns >= STAGES) ns -= STAGES;
            load_tiles(ns, kt + 2);
        }
        CP_COMMIT();

        // mma for kk=0
        #pragma unroll
        for (int mf = 0; mf < 4; mf++)
            #pragma unroll
            for (int nf = 0; nf < 8; nf++)
                mma_f16(acc[mf][nf], af[mf], bf[nf]);

        // remaining kk slices
        #pragma unroll
        for (int kk = 16; kk < BKH; kk += 16) {
            load_frags(aS, bS, kk, af, bf);
            #pragma unroll
            for (int mf = 0; mf < 4; mf++)
                #pragma unroll
                for (int nf = 0; nf < 8; nf++)
                    mma_f16(acc[mf][nf], af[mf], bf[nf]);
        }
        if (++stage >= STAGES) stage = 0;
    }

    // ---- epilogue ----
    __half* Ch; float* Cf; int Nout = N;
    int ncol0 = n0;
    float* rsum = nullptr;
    if (MODE == 0) {            // QKV: route by 1024-block
        const int blk = n0 >> 10;
        Ch = (__half*)(blk == 0 ? C0 : (blk == 1 ? C1 : C2));
        Ch += (long long)bz * strC;
        ncol0 = n0 & 1023; Nout = DM;
    } else if (MODE == 1) {
        Ch = (__half*)C0 + (long long)bz * strC;
        rsum = (float*)C1 + (long long)bz * SEQ;
    } else if (MODE == 2) {
        Ch = (__half*)C0 + (long long)bz * strC;
        rsum = (float*)bias + (long long)bz * SEQ;   // rowsum passed via bias slot
    } else {
        Cf = (float*)C0 + (long long)bz * strC;
    }

    #pragma unroll
    for (int mf = 0; mf < 4; mf++) {
        const int r0 = m0 + warp_m * 64 + mf * 16 + gid;
        float inv0 = 1.f, inv1 = 1.f;
        if (MODE == 2) {
            inv0 = 1.f / rsum[r0];
            inv1 = 1.f / rsum[r0 + 8];
        }
        float psum0 = 0.f, psum8 = 0.f;   // MODE==1 row partial sums
        #pragma unroll
        for (int nf = 0; nf < 8; nf++) {
            const int nrel = warp_n * 64 + nf * 8 + 2 * tig;
            const int n = ncol0 + nrel;
            float bx = 0.f, by = 0.f;
            if (MODE == 0 || MODE == 3) {
                float2 bv = *(const float2*)&bias[n0 + nrel];
                bx = bv.x; by = bv.y;
            }
            float c0 = acc[mf][nf][0] * scale + bx;
            float c1 = acc[mf][nf][1] * scale + by;
            float c2 = acc[mf][nf][2] * scale + bx;
            float c3 = acc[mf][nf][3] * scale + by;
            if (MODE == 1) {
                __half2 e01 = __floats2half2_rn(__expf(c0), __expf(c1));
                __half2 e23 = __floats2half2_rn(__expf(c2), __expf(c3));
                float2 f01 = __half22float2(e01);
                float2 f23 = __half22float2(e23);
                psum0 += f01.x + f01.y;
                psum8 += f23.x + f23.y;
                *(__half2*)&Ch[(long long)r0 * Nout + n]       = e01;
                *(__half2*)&Ch[(long long)(r0 + 8) * Nout + n] = e23;
            } else if (MODE == 2) {
                *(__half2*)&Ch[(long long)r0 * Nout + n]       = __floats2half2_rn(c0 * inv0, c1 * inv0);
                *(__half2*)&Ch[(long long)(r0 + 8) * Nout + n] = __floats2half2_rn(c2 * inv1, c3 * inv1);
            } else if (MODE == 0) {
                *(__half2*)&Ch[(long long)r0 * Nout + n]       = __floats2half2_rn(c0, c1);
                *(__half2*)&Ch[(long long)(r0 + 8) * Nout + n] = __floats2half2_rn(c2, c3);
            } else {
                *(float2*)&Cf[(long long)r0 * Nout + n]       = make_float2(c0, c1);
                *(float2*)&Cf[(long long)(r0 + 8) * Nout + n] = make_float2(c2, c3);
            }
        }
        if (MODE == 1) {
            psum0 += __shfl_xor_sync(0xffffffffu, psum0, 1);
            psum0 += __shfl_xor_sync(0xffffffffu, psum0, 2);
            psum8 += __shfl_xor_sync(0xffffffffu, psum8, 1);
            psum8 += __shfl_xor_sync(0xffffffffu, psum8, 2);
            if (tig == 0) {
                atomicAdd(&rsum[r0], psum0);
                atomicAdd(&rsum[r0 + 8], psum8);
            }
        }
    }
}

// ---------------------------------------------------------------------------
// Fused prepass (one launch): f2h + 4x weight transpose + bias concat + rs zero
// ---------------------------------------------------------------------------
struct PrepassArgs {
    const float* x;  __half* xh;
    const float* w[4]; __half* wt[4];
    const float* bq; const float* bk; const float* bv;
    float* bqkv; float* rs;
};

__global__ __launch_bounds__(256)
void prepass_all(PrepassArgs pa)
{
    const int b = blockIdx.x;
    const int t = threadIdx.x;
    if (b < 4096) {
        long long i = ((long long)b * 256 + t) * 8;
        float4 a = *(const float4*)(pa.x + i);
        float4 c = *(const float4*)(pa.x + i + 4);
        __half2 h[4];
        h[0] = __floats2half2_rn(a.x, a.y);
        h[1] = __floats2half2_rn(a.z, a.w);
        h[2] = __floats2half2_rn(c.x, c.y);
        h[3] = __floats2half2_rn(c.z, c.w);
        *(uint4*)(pa.xh + i) = *(uint4*)h;
    } else if (b < 8192) {
        __shared__ float tl[32][33];
        const int bb = b - 4096;
        const int wsel = bb >> 10;
        const int tile = bb & 1023;
        const int bx = tile & 31, by = tile >> 5;
        const float* in = pa.w[wsel];
        __half* outw = pa.wt[wsel];
        const int tx = t & 31, ty = t >> 5;
        const int c = bx * 32 + tx;
        const int r0 = by * 32;
        #pragma unroll
        for (int i = 0; i < 32; i += 8)
            tl[ty + i][tx] = in[(long long)(r0 + ty + i) * DM + c];
        __syncthreads();
        const int r2 = r0 + tx;
        const int c2 = bx * 32;
        #pragma unroll
        for (int i = 0; i < 32; i += 8)
            outw[(long long)(c2 + ty + i) * DM + r2] = __float2half_rn(tl[tx][ty + i]);
    } else {
        const int i = (b - 8192) * 256 + t;
        if (i < 3 * DM) {
            const float* src = (i < DM) ? pa.bq : (i < 2 * DM ? pa.bk : pa.bv);
            pa.bqkv[i] = src[i & (DM - 1)];
        }
        const int j = i - 3 * DM;
        if (j >= 0 && j < BATCH * SEQ) pa.rs[j] = 0.f;
    }
}

// ---------------------------------------------------------------------------
extern "C" void kernel_launch(void* const* d_in, const int* in_sizes, int n_in,
                              void* d_out, int out_size)
{
    const float* x  = (const float*)d_in[0];
    const float* wq = (const float*)d_in[1];
    const float* bq = (const float*)d_in[2];
    const float* wk = (const float*)d_in[3];
    const float* bk = (const float*)d_in[4];
    const float* wv = (const float*)d_in[5];
    const float* bv = (const float*)d_in[6];
    const float* wo = (const float*)d_in[7];
    const float* bo = (const float*)d_in[8];
    float* out = (float*)d_out;

    __half *xh, *wqkvt, *wot, *q, *k, *v, *pm, *o;
    float *bqkv, *rs;
    cudaGetSymbolAddress((void**)&xh,    g_xh);
    cudaGetSymbolAddress((void**)&wqkvt, g_wqkvt);
    cudaGetSymbolAddress((void**)&wot,   g_wot);
    cudaGetSymbolAddress((void**)&bqkv,  g_bqkv);
    cudaGetSymbolAddress((void**)&q,   g_q);
    cudaGetSymbolAddress((void**)&k,   g_k);
    cudaGetSymbolAddress((void**)&v,   g_v);
    cudaGetSymbolAddress((void**)&pm,  g_p);
    cudaGetSymbolAddress((void**)&rs,  g_rs);
    cudaGetSymbolAddress((void**)&o,   g_o);

    cudaFuncSetAttribute(gemm_h<0>, cudaFuncAttributeMaxDynamicSharedMemorySize, GEMM_SMEM);
    cudaFuncSetAttribute(gemm_h<1>, cudaFuncAttributeMaxDynamicSharedMemorySize, GEMM_SMEM);
    cudaFuncSetAttribute(gemm_h<2>, cudaFuncAttributeMaxDynamicSharedMemorySize, GEMM_SMEM);
    cudaFuncSetAttribute(gemm_h<3>, cudaFuncAttributeMaxDynamicSharedMemorySize, GEMM_SMEM);

    const int MTOT = BATCH * SEQ;      // 8192
    const float iscale = 0.03125f;     // 1/sqrt(1024)

    // --- fused prepass ---
    PrepassArgs pa;
    pa.x = x; pa.xh = xh;
    pa.w[0] = wq; pa.w[1] = wk; pa.w[2] = wv; pa.w[3] = wo;
    pa.wt[0] = wqkvt; pa.wt[1] = wqkvt + DM * DM; pa.wt[2] = wqkvt + 2 * DM * DM;
    pa.wt[3] = wot;
    pa.bq = bq; pa.bk = bk; pa.bv = bv; pa.bqkv = bqkv; pa.rs = rs;
    prepass_all<<<8192 + 44, 256>>>(pa);

    dim3 blk(NTHR);

    // fused QKV projection: N=3072, routed epilogue
    dim3 gqkv(3 * DM / BN, MTOT / BM, 1);    // (12, 64)
    gemm_h<0><<<gqkv, blk, GEMM_SMEM>>>(xh, wqkvt, bqkv, q, k, v,
                                        3 * DM, DM, 1.f, 0, 0, 0);

    // exp(scores) = exp(q @ k^T * (1/32)) -> half, + row sums (atomic)
    dim3 gsc(SEQ / BN, SEQ / BM, BATCH);     // (8, 16, 4)
    gemm_h<1><<<gsc, blk, GEMM_SMEM>>>(q, k, nullptr, pm, rs, nullptr,
                                       SEQ, DM, iscale,
                                       (long long)SEQ * DM, (long long)SEQ * DM,
                                       (long long)SEQ * SEQ);

    // o = (expS @ v) / rowsum  (B = v via ldmatrix.trans) -> half
    dim3 gav(DM / BN, SEQ / BM, BATCH);      // (4, 16, 4)
    gemm_h<2><<<gav, blk, GEMM_SMEM>>>(pm, v, rs, o, nullptr, nullptr,
                                       DM, SEQ, 1.f,
                                       (long long)SEQ * SEQ, (long long)SEQ * DM,
                                       (long long)SEQ * DM);

    // out = o @ wo + bo -> fp32
    dim3 gop(DM / BN, MTOT / BM, 1);         // (4, 64)
    gemm_h<3><<<gop, blk, GEMM_SMEM>>>(o, wot, bo, out, nullptr, nullptr,
                                       DM, DM, 1.f, 0, 0, 0);
}

// round 14
// speedup vs baseline: 1.3042x; 1.0487x over previous
#include <cuda_runtime.h>
#include <cuda_fp16.h>
#include <cstdint>

// ---------------------------------------------------------------------------
// SelfAttention  x[4,2048,1024] -> out[4,2048,1024]
// Round 14: r13 + cp.async prefetch split into 4 parts, one issued between
//           each kk-slice's ldmatrix and MMA burst (spread MIO pressure;
//           r13 proved cp.async/ldmatrix MIO ordering costs HMMA issue).
// ---------------------------------------------------------------------------

#define BATCH 4
#define SEQ   2048
#define DM    1024

// ---- scratch (__device__ globals) ----
__device__ __half g_xh   [(long long)BATCH * SEQ * DM];
__device__ __half g_wqkvt[3 * DM * DM];
__device__ __half g_wot  [DM * DM];
__device__ float  g_bqkv [3 * DM];
__device__ __half g_q  [(long long)BATCH * SEQ * DM];
__device__ __half g_k  [(long long)BATCH * SEQ * DM];
__device__ __half g_v  [(long long)BATCH * SEQ * DM];
__device__ __half g_p  [(long long)BATCH * SEQ * SEQ];   // exp(scores), half
__device__ float  g_rs [BATCH * SEQ];                    // row sums
__device__ __half g_o  [(long long)BATCH * SEQ * DM];

// ---- PTX helpers ----
__device__ __forceinline__ void cp_async16(void* smem, const void* gmem) {
    uint32_t s = (uint32_t)__cvta_generic_to_shared(smem);
    asm volatile("cp.async.ca.shared.global [%0], [%1], 16;\n" :: "r"(s), "l"(gmem));
}
#define CP_COMMIT() asm volatile("cp.async.commit_group;\n" ::: "memory")
#define CP_WAIT1()  asm volatile("cp.async.wait_group 1;\n" ::: "memory")

__device__ __forceinline__ void mma_f16(float* c, const uint32_t* a, const uint32_t* b) {
    asm volatile(
        "mma.sync.aligned.m16n8k16.row.col.f32.f16.f16.f32 "
        "{%0,%1,%2,%3}, {%4,%5,%6,%7}, {%8,%9}, {%0,%1,%2,%3};\n"
        : "+f"(c[0]), "+f"(c[1]), "+f"(c[2]), "+f"(c[3])
        : "r"(a[0]), "r"(a[1]), "r"(a[2]), "r"(a[3]), "r"(b[0]), "r"(b[1]));
}

__device__ __forceinline__ void ldmatrix_x4(uint32_t* r, uint32_t saddr) {
    asm volatile("ldmatrix.sync.aligned.m8n8.x4.shared.b16 {%0,%1,%2,%3}, [%4];"
        : "=r"(r[0]), "=r"(r[1]), "=r"(r[2]), "=r"(r[3]) : "r"(saddr));
}
__device__ __forceinline__ void ldmatrix_x4_trans(uint32_t* r, uint32_t saddr) {
    asm volatile("ldmatrix.sync.aligned.m8n8.x4.trans.shared.b16 {%0,%1,%2,%3}, [%4];"
        : "=r"(r[0]), "=r"(r[1]), "=r"(r[2]), "=r"(r[3]) : "r"(saddr));
}

// ---------------------------------------------------------------------------
// FP16 GEMM: C = scale*(A[M,K] @ op(B)) [+ bias]
// CTA 128x256x64, 256 thr, 8 warps (2x4), warp tile 64x64, 3-stage cp.async.
// MODE: 0=QKV (B=[N,K] NT; half out, bias, route by n-block)
//       1=scores->exp (B=[N,K] NT; half out = exp(acc*scale); atomic row sums)
//       2=PV (B=v[K,N] via ldmatrix.trans; half out, /rowsum via 'bias' slot)
//       3=outproj (B=[N,K] NT; f32 out, bias)
// ---------------------------------------------------------------------------
#define BM 128
#define BN 256
#define BKH 64                   // K halves per stage
#define PITCH 72                 // NT pitch: 144B rows (conflict-free)
#define VPITCH 264               // MODE2 B pitch: 528B rows (conflict-free)
#define ASTH (BM * PITCH)        // 9216 halves
#define BSTH (BN * PITCH)        // 18432 halves (MODE2 uses BKH*VPITCH=16896)
#define STG_H (ASTH + BSTH)      // 27648 halves per stage
#define STAGES 3
#define GEMM_SMEM (STAGES * STG_H * 2)   // 165888 bytes
#define NTHR 256

template<int MODE>
__global__ __launch_bounds__(NTHR, 1)
void gemm_h(const __half* __restrict__ A, const __half* __restrict__ B,
            const float* __restrict__ bias,
            void* __restrict__ C0, void* __restrict__ C1, void* __restrict__ C2,
            int N, int K, float scale,
            long long strA, long long strB, long long strC)
{
    extern __shared__ __half smem[];
    const uint32_t sbase = (uint32_t)__cvta_generic_to_shared(smem);

    const int bz = blockIdx.z;
    A += (long long)bz * strA;
    B += (long long)bz * strB;

    const int m0 = blockIdx.y * BM;
    const int n0 = blockIdx.x * BN;
    const int t    = threadIdx.x;
    const int lane = t & 31;
    const int wid  = t >> 5;
    const int warp_m = wid & 1;     // 0..1 (64 rows)
    const int warp_n = wid >> 1;    // 0..3 (64 cols)
    const int gid = lane >> 2;
    const int tig = lane & 3;

    // ldmatrix per-lane source coords
    const int rowA = warp_m * 64 + (lane & 15);      // + mf*16
    const int colA = (lane >> 4) * 8;                // + kk
    const int gB   = lane >> 3;
    const int rowB = warp_n * 64 + (gB >> 1) * 8 + (lane & 7);  // NT: + p*16
    const int colB = (gB & 1) * 8;
    // MODE2 trans coords
    const int kln = lane & 15;
    const int nln = (lane >> 4) * 8;

    float acc[4][8][4];
    #pragma unroll
    for (int mf = 0; mf < 4; mf++)
        #pragma unroll
        for (int nf = 0; nf < 8; nf++)
            #pragma unroll
            for (int r = 0; r < 4; r++) acc[mf][nf][r] = 0.f;

    const int KT = K / BKH;

    // issue 1/4 of the stage prefetch: A chunk 'part', B chunks 2*part, 2*part+1
    auto load_part = [&](int stage, int kt, int part) {
        const int k0 = kt * BKH;
        __half* dA = smem + stage * STG_H;
        __half* dB = dA + ASTH;
        {
            int ch = t + part * NTHR;
            int row = ch >> 3, c8 = (ch & 7) * 8;
            cp_async16(dA + row * PITCH + c8, A + (long long)(m0 + row) * K + k0 + c8);
        }
        #pragma unroll
        for (int j = 0; j < 2; j++) {
            int ch = t + (2 * part + j) * NTHR;
            if (MODE == 2) {
                int row = ch >> 5, c8 = (ch & 31) * 8;
                cp_async16(dB + row * VPITCH + c8,
                           B + (long long)(k0 + row) * DM + n0 + c8);
            } else {
                int row = ch >> 3, c8 = (ch & 7) * 8;
                cp_async16(dB + row * PITCH + c8, B + (long long)(n0 + row) * K + k0 + c8);
            }
        }
    };
    auto load_tiles = [&](int stage, int kt) {
        #pragma unroll
        for (int p = 0; p < 4; p++) load_part(stage, kt, p);
    };

    // fragment loader for one kk16 slice
    auto load_frags = [&](uint32_t aS, uint32_t bS, int kk,
                          uint32_t (&af)[4][4], uint32_t (&bf)[8][2]) {
        #pragma unroll
        for (int mf = 0; mf < 4; mf++)
            ldmatrix_x4(af[mf], aS + (uint32_t)(((rowA + mf * 16) * PITCH) + kk + colA) * 2);
        #pragma unroll
        for (int p = 0; p < 4; p++) {
            uint32_t r[4];
            if (MODE == 2) {
                ldmatrix_x4_trans(r, bS + (uint32_t)((kk + kln) * VPITCH +
                                       warp_n * 64 + p * 16 + nln) * 2);
            } else {
                ldmatrix_x4(r, bS + (uint32_t)(((rowB + p * 16) * PITCH) + kk + colB) * 2);
            }
            bf[2 * p][0] = r[0]; bf[2 * p][1] = r[1];
            bf[2 * p + 1][0] = r[2]; bf[2 * p + 1][1] = r[3];
        }
    };

    // prologue: stages 0,1
    load_tiles(0, 0); CP_COMMIT();
    if (1 < KT) load_tiles(1, 1);
    CP_COMMIT();

    int stage = 0;
    for (int kt = 0; kt < KT; kt++) {
        CP_WAIT1();
        __syncthreads();          // stage kt ready; all warps done with kt-1

        const uint32_t aS = sbase + (stage * STG_H) * 2;
        const uint32_t bS = aS + ASTH * 2;

        const bool pf = (kt + 2 < KT);
        int ns = stage + 2; if (ns >= STAGES) ns -= STAGES;

        uint32_t af[4][4];
        uint32_t bf[8][2];
        #pragma unroll
        for (int ki = 0; ki < BKH / 16; ki++) {
            load_frags(aS, bS, ki * 16, af, bf);
            if (pf) load_part(ns, kt + 2, ki);   // 3 cp.asyncs in ldmatrix shadow
            #pragma unroll
            for (int mf = 0; mf < 4; mf++)
                #pragma unroll
                for (int nf = 0; nf < 8; nf++)
                    mma_f16(acc[mf][nf], af[mf], bf[nf]);
        }
        CP_COMMIT();

        if (++stage >= STAGES) stage = 0;
    }

    // ---- epilogue ----
    __half* Ch; float* Cf; int Nout = N;
    int ncol0 = n0;
    float* rsum = nullptr;
    if (MODE == 0) {            // QKV: route by 1024-block
        const int blk = n0 >> 10;
        Ch = (__half*)(blk == 0 ? C0 : (blk == 1 ? C1 : C2));
        Ch += (long long)bz * strC;
        ncol0 = n0 & 1023; Nout = DM;
    } else if (MODE == 1) {
        Ch = (__half*)C0 + (long long)bz * strC;
        rsum = (float*)C1 + (long long)bz * SEQ;
    } else if (MODE == 2) {
        Ch = (__half*)C0 + (long long)bz * strC;
        rsum = (float*)bias + (long long)bz * SEQ;   // rowsum passed via bias slot
    } else {
        Cf = (float*)C0 + (long long)bz * strC;
    }

    #pragma unroll
    for (int mf = 0; mf < 4; mf++) {
        const int r0 = m0 + warp_m * 64 + mf * 16 + gid;
        float inv0 = 1.f, inv1 = 1.f;
        if (MODE == 2) {
            inv0 = 1.f / rsum[r0];
            inv1 = 1.f / rsum[r0 + 8];
        }
        float psum0 = 0.f, psum8 = 0.f;   // MODE==1 row partial sums
        #pragma unroll
        for (int nf = 0; nf < 8; nf++) {
            const int nrel = warp_n * 64 + nf * 8 + 2 * tig;
            const int n = ncol0 + nrel;
            float bx = 0.f, by = 0.f;
            if (MODE == 0 || MODE == 3) {
                float2 bv = *(const float2*)&bias[n0 + nrel];
                bx = bv.x; by = bv.y;
            }
            float c0 = acc[mf][nf][0] * scale + bx;
            float c1 = acc[mf][nf][1] * scale + by;
            float c2 = acc[mf][nf][2] * scale + bx;
            float c3 = acc[mf][nf][3] * scale + by;
            if (MODE == 1) {
                __half2 e01 = __floats2half2_rn(__expf(c0), __expf(c1));
                __half2 e23 = __floats2half2_rn(__expf(c2), __expf(c3));
                float2 f01 = __half22float2(e01);
                float2 f23 = __half22float2(e23);
                psum0 += f01.x + f01.y;
                psum8 += f23.x + f23.y;
                *(__half2*)&Ch[(long long)r0 * Nout + n]       = e01;
                *(__half2*)&Ch[(long long)(r0 + 8) * Nout + n] = e23;
            } else if (MODE == 2) {
                *(__half2*)&Ch[(long long)r0 * Nout + n]       = __floats2half2_rn(c0 * inv0, c1 * inv0);
                *(__half2*)&Ch[(long long)(r0 + 8) * Nout + n] = __floats2half2_rn(c2 * inv1, c3 * inv1);
            } else if (MODE == 0) {
                *(__half2*)&Ch[(long long)r0 * Nout + n]       = __floats2half2_rn(c0, c1);
                *(__half2*)&Ch[(long long)(r0 + 8) * Nout + n] = __floats2half2_rn(c2, c3);
            } else {
                *(float2*)&Cf[(long long)r0 * Nout + n]       = make_float2(c0, c1);
                *(float2*)&Cf[(long long)(r0 + 8) * Nout + n] = make_float2(c2, c3);
            }
        }
        if (MODE == 1) {
            psum0 += __shfl_xor_sync(0xffffffffu, psum0, 1);
            psum0 += __shfl_xor_sync(0xffffffffu, psum0, 2);
            psum8 += __shfl_xor_sync(0xffffffffu, psum8, 1);
            psum8 += __shfl_xor_sync(0xffffffffu, psum8, 2);
            if (tig == 0) {
                atomicAdd(&rsum[r0], psum0);
                atomicAdd(&rsum[r0 + 8], psum8);
            }
        }
    }
}

// ---------------------------------------------------------------------------
// Fused prepass (one launch): f2h + 4x weight transpose + bias concat + rs zero
// ---------------------------------------------------------------------------
struct PrepassArgs {
    const float* x;  __half* xh;
    const float* w[4]; __half* wt[4];
    const float* bq; const float* bk; const float* bv;
    float* bqkv; float* rs;
};

__global__ __launch_bounds__(256)
void prepass_all(PrepassArgs pa)
{
    const int b = blockIdx.x;
    const int t = threadIdx.x;
    if (b < 4096) {
        long long i = ((long long)b * 256 + t) * 8;
        float4 a = *(const float4*)(pa.x + i);
        float4 c = *(const float4*)(pa.x + i + 4);
        __half2 h[4];
        h[0] = __floats2half2_rn(a.x, a.y);
        h[1] = __floats2half2_rn(a.z, a.w);
        h[2] = __floats2half2_rn(c.x, c.y);
        h[3] = __floats2half2_rn(c.z, c.w);
        *(uint4*)(pa.xh + i) = *(uint4*)h;
    } else if (b < 8192) {
        __shared__ float tl[32][33];
        const int bb = b - 4096;
        const int wsel = bb >> 10;
        const int tile = bb & 1023;
        const int bx = tile & 31, by = tile >> 5;
        const float* in = pa.w[wsel];
        __half* outw = pa.wt[wsel];
        const int tx = t & 31, ty = t >> 5;
        const int c = bx * 32 + tx;
        const int r0 = by * 32;
        #pragma unroll
        for (int i = 0; i < 32; i += 8)
            tl[ty + i][tx] = in[(long long)(r0 + ty + i) * DM + c];
        __syncthreads();
        const int r2 = r0 + tx;
        const int c2 = bx * 32;
        #pragma unroll
        for (int i = 0; i < 32; i += 8)
            outw[(long long)(c2 + ty + i) * DM + r2] = __float2half_rn(tl[tx][ty + i]);
    } else {
        const int i = (b - 8192) * 256 + t;
        if (i < 3 * DM) {
            const float* src = (i < DM) ? pa.bq : (i < 2 * DM ? pa.bk : pa.bv);
            pa.bqkv[i] = src[i & (DM - 1)];
        }
        const int j = i - 3 * DM;
        if (j >= 0 && j < BATCH * SEQ) pa.rs[j] = 0.f;
    }
}

// ---------------------------------------------------------------------------
extern "C" void kernel_launch(void* const* d_in, const int* in_sizes, int n_in,
                              void* d_out, int out_size)
{
    const float* x  = (const float*)d_in[0];
    const float* wq = (const float*)d_in[1];
    const float* bq = (const float*)d_in[2];
    const float* wk = (const float*)d_in[3];
    const float* bk = (const float*)d_in[4];
    const float* wv = (const float*)d_in[5];
    const float* bv = (const float*)d_in[6];
    const float* wo = (const float*)d_in[7];
    const float* bo = (const float*)d_in[8];
    float* out = (float*)d_out;

    __half *xh, *wqkvt, *wot, *q, *k, *v, *pm, *o;
    float *bqkv, *rs;
    cudaGetSymbolAddress((void**)&xh,    g_xh);
    cudaGetSymbolAddress((void**)&wqkvt, g_wqkvt);
    cudaGetSymbolAddress((void**)&wot,   g_wot);
    cudaGetSymbolAddress((void**)&bqkv,  g_bqkv);
    cudaGetSymbolAddress((void**)&q,   g_q);
    cudaGetSymbolAddress((void**)&k,   g_k);
    cudaGetSymbolAddress((void**)&v,   g_v);
    cudaGetSymbolAddress((void**)&pm,  g_p);
    cudaGetSymbolAddress((void**)&rs,  g_rs);
    cudaGetSymbolAddress((void**)&o,   g_o);

    cudaFuncSetAttribute(gemm_h<0>, cudaFuncAttributeMaxDynamicSharedMemorySize, GEMM_SMEM);
    cudaFuncSetAttribute(gemm_h<1>, cudaFuncAttributeMaxDynamicSharedMemorySize, GEMM_SMEM);
    cudaFuncSetAttribute(gemm_h<2>, cudaFuncAttributeMaxDynamicSharedMemorySize, GEMM_SMEM);
    cudaFuncSetAttribute(gemm_h<3>, cudaFuncAttributeMaxDynamicSharedMemorySize, GEMM_SMEM);

    const int MTOT = BATCH * SEQ;      // 8192
    const float iscale = 0.03125f;     // 1/sqrt(1024)

    // --- fused prepass ---
    PrepassArgs pa;
    pa.x = x; pa.xh = xh;
    pa.w[0] = wq; pa.w[1] = wk; pa.w[2] = wv; pa.w[3] = wo;
    pa.wt[0] = wqkvt; pa.wt[1] = wqkvt + DM * DM; pa.wt[2] = wqkvt + 2 * DM * DM;
    pa.wt[3] = wot;
    pa.bq = bq; pa.bk = bk; pa.bv = bv; pa.bqkv = bqkv; pa.rs = rs;
    prepass_all<<<8192 + 44, 256>>>(pa);

    dim3 blk(NTHR);

    // fused QKV projection: N=3072, routed epilogue
    dim3 gqkv(3 * DM / BN, MTOT / BM, 1);    // (12, 64)
    gemm_h<0><<<gqkv, blk, GEMM_SMEM>>>(xh, wqkvt, bqkv, q, k, v,
                                        3 * DM, DM, 1.f, 0, 0, 0);

    // exp(scores) = exp(q @ k^T * (1/32)) -> half, + row sums (atomic)
    dim3 gsc(SEQ / BN, SEQ / BM, BATCH);     // (8, 16, 4)
    gemm_h<1><<<gsc, blk, GEMM_SMEM>>>(q, k, nullptr, pm, rs, nullptr,
                                       SEQ, DM, iscale,
                                       (long long)SEQ * DM, (long long)SEQ * DM,
                                       (long long)SEQ * SEQ);

    // o = (expS @ v) / rowsum  (B = v via ldmatrix.trans) -> half
    dim3 gav(DM / BN, SEQ / BM, BATCH);      // (4, 16, 4)
    gemm_h<2><<<gav, blk, GEMM_SMEM>>>(pm, v, rs, o, nullptr, nullptr,
                                       DM, SEQ, 1.f,
                                       (long long)SEQ * SEQ, (long long)SEQ * DM,
                                       (long long)SEQ * DM);

    // out = o @ wo + bo -> fp32
    dim3 gop(DM / BN, MTOT / BM, 1);         // (4, 64)
    gemm_h<3><<<gop, blk, GEMM_SMEM>>>(o, wot, bo, out, nullptr, nullptr,
                                       DM, DM, 1.f, 0, 0, 0);
}